// round 2
// baseline (speedup 1.0000x reference)
#include <cuda_runtime.h>
#include <math.h>

#define N_NODES 50000
#define FEAT    128
#define MAX_E   800000

// ---- scratch (static __device__ arrays; no runtime allocation) ----
__device__ float g_bufT[N_NODES * FEAT];   // post-GEMM features
__device__ float g_bufH[N_NODES * FEAT];   // post-aggregation features
__device__ int   g_deg[N_NODES];           // in-degree (edges only)
__device__ float g_dis[N_NODES];           // rsqrt(deg+1)
__device__ int   g_rowoff[N_NODES + 1];    // CSR row offsets (by dst)
__device__ int   g_cursor[N_NODES];        // fill cursors
__device__ int   g_csr[MAX_E];             // src ids grouped by dst

// ------------------------------------------------------------------
__global__ void k_zero_deg() {
    int i = blockIdx.x * blockDim.x + threadIdx.x;
    if (i < N_NODES) g_deg[i] = 0;
}

__global__ void k_count(const int* __restrict__ dst, int E) {
    int i = blockIdx.x * blockDim.x + threadIdx.x;
    if (i < E) atomicAdd(&g_deg[dst[i]], 1);
}

__global__ void k_dis() {
    int i = blockIdx.x * blockDim.x + threadIdx.x;
    if (i < N_NODES) g_dis[i] = rsqrtf((float)(g_deg[i] + 1));  // +1 self-loop
}

// single-block exclusive scan of g_deg -> g_rowoff, also seeds g_cursor
__global__ void k_scan() {
    __shared__ int wsum[32];
    __shared__ int carry;
    int lane = threadIdx.x & 31, wid = threadIdx.x >> 5;
    if (threadIdx.x == 0) carry = 0;
    __syncthreads();
    for (int base = 0; base < N_NODES; base += 1024) {
        int i = base + (int)threadIdx.x;
        int v = (i < N_NODES) ? g_deg[i] : 0;
        int s = v;
        #pragma unroll
        for (int d = 1; d < 32; d <<= 1) {
            int t = __shfl_up_sync(0xffffffffu, s, d);
            if (lane >= d) s += t;
        }
        if (lane == 31) wsum[wid] = s;
        __syncthreads();
        if (wid == 0) {
            int ws = wsum[lane];
            #pragma unroll
            for (int d = 1; d < 32; d <<= 1) {
                int t = __shfl_up_sync(0xffffffffu, ws, d);
                if (lane >= d) ws += t;
            }
            wsum[lane] = ws;
        }
        __syncthreads();
        int off  = carry + (wid > 0 ? wsum[wid - 1] : 0);
        int excl = off + s - v;
        if (i < N_NODES) { g_rowoff[i] = excl; g_cursor[i] = excl; }
        __syncthreads();
        if (threadIdx.x == 0) carry += wsum[31];
        __syncthreads();
    }
    if (threadIdx.x == 0) g_rowoff[N_NODES] = carry;
}

__global__ void k_fill(const int* __restrict__ src, const int* __restrict__ dst, int E) {
    int i = blockIdx.x * blockDim.x + threadIdx.x;
    if (i < E) {
        int d = dst[i];
        int p = atomicAdd(&g_cursor[d], 1);
        g_csr[p] = src[i];
    }
}

// ------------------------------------------------------------------
// GEMM: C[nrows,128] = A[nrows,128] @ W[128,128]   (fp32, shared-tiled)
// BM=64 rows/block, BK=16, 256 threads, each thread 8x4 outputs.
#define BM 64
#define BK 16
__global__ __launch_bounds__(256) void k_gemm(const float* __restrict__ A,
                                              const float* __restrict__ W,
                                              float* __restrict__ C, int nrows) {
    __shared__ float As[BK][BM];     // k-major (transposed) for float4 row reads
    __shared__ float Bs[BK][FEAT];
    int t    = threadIdx.x;
    int row0 = blockIdx.x * BM;
    int ty   = t >> 5;   // 0..7  -> rows ty*8..ty*8+7
    int tx   = t & 31;   // 0..31 -> cols tx*4..tx*4+3

    float acc[8][4];
    #pragma unroll
    for (int r = 0; r < 8; r++)
        #pragma unroll
        for (int c = 0; c < 4; c++) acc[r][c] = 0.0f;

    for (int k0 = 0; k0 < FEAT; k0 += BK) {
        // load A tile (64 x 16), transpose into As[k][row]
        {
            int r  = t >> 2;
            int c4 = (t & 3) * 4;
            int gr = row0 + r;
            float4 a = make_float4(0.f, 0.f, 0.f, 0.f);
            if (gr < nrows) a = *(const float4*)&A[gr * FEAT + k0 + c4];
            As[c4 + 0][r] = a.x; As[c4 + 1][r] = a.y;
            As[c4 + 2][r] = a.z; As[c4 + 3][r] = a.w;
        }
        // load B tile (16 x 128)
        #pragma unroll
        for (int it = 0; it < 2; it++) {
            int idx = t + it * 256;       // float4 slot 0..511
            int kk  = idx >> 5;
            int c4  = (idx & 31) * 4;
            *(float4*)&Bs[kk][c4] = *(const float4*)&W[(k0 + kk) * FEAT + c4];
        }
        __syncthreads();

        #pragma unroll
        for (int kk = 0; kk < BK; kk++) {
            float4 a0 = *(const float4*)&As[kk][ty * 8];
            float4 a1 = *(const float4*)&As[kk][ty * 8 + 4];
            float4 b  = *(const float4*)&Bs[kk][tx * 4];
            float ar[8] = {a0.x, a0.y, a0.z, a0.w, a1.x, a1.y, a1.z, a1.w};
            float bc[4] = {b.x, b.y, b.z, b.w};
            #pragma unroll
            for (int r = 0; r < 8; r++)
                #pragma unroll
                for (int c = 0; c < 4; c++) acc[r][c] = fmaf(ar[r], bc[c], acc[r][c]);
        }
        __syncthreads();
    }

    #pragma unroll
    for (int r = 0; r < 8; r++) {
        int gr = row0 + ty * 8 + r;
        if (gr < nrows) {
            float4 v = make_float4(acc[r][0], acc[r][1], acc[r][2], acc[r][3]);
            *(float4*)&C[gr * FEAT + tx * 4] = v;
        }
    }
}

// ------------------------------------------------------------------
// Aggregation: one warp per dst node. acc = dis[d]^2*T[d] + sum norm_e*T[src_e]
// then bias + ELU -> Hout. Unrolled by 2 for memory-level parallelism.
__device__ __forceinline__ float elu1(float v) {
    return v > 0.0f ? v : expm1f(v);
}

__global__ __launch_bounds__(256) void k_agg(const float* __restrict__ T,
                                             const float* __restrict__ bias,
                                             float* __restrict__ Hout) {
    int warp = (int)((blockIdx.x * blockDim.x + threadIdx.x) >> 5);
    int lane = threadIdx.x & 31;
    if (warp >= N_NODES) return;
    int node = warp;
    float dd = g_dis[node];

    float4 acc = *(const float4*)&T[node * FEAT + lane * 4];
    float ws = dd * dd;                       // self-loop weight
    acc.x *= ws; acc.y *= ws; acc.z *= ws; acc.w *= ws;

    int beg = g_rowoff[node];
    int end = g_rowoff[node + 1];
    int e = beg;
    for (; e + 1 < end; e += 2) {
        int s0 = g_csr[e];
        int s1 = g_csr[e + 1];
        float w0 = g_dis[s0] * dd;
        float w1 = g_dis[s1] * dd;
        float4 v0 = *(const float4*)&T[s0 * FEAT + lane * 4];
        float4 v1 = *(const float4*)&T[s1 * FEAT + lane * 4];
        acc.x = fmaf(w0, v0.x, fmaf(w1, v1.x, acc.x));
        acc.y = fmaf(w0, v0.y, fmaf(w1, v1.y, acc.y));
        acc.z = fmaf(w0, v0.z, fmaf(w1, v1.z, acc.z));
        acc.w = fmaf(w0, v0.w, fmaf(w1, v1.w, acc.w));
    }
    if (e < end) {
        int s0 = g_csr[e];
        float w0 = g_dis[s0] * dd;
        float4 v0 = *(const float4*)&T[s0 * FEAT + lane * 4];
        acc.x = fmaf(w0, v0.x, acc.x);
        acc.y = fmaf(w0, v0.y, acc.y);
        acc.z = fmaf(w0, v0.z, acc.z);
        acc.w = fmaf(w0, v0.w, acc.w);
    }

    float4 b = *(const float4*)&bias[lane * 4];
    float4 r;
    r.x = elu1(acc.x + b.x);
    r.y = elu1(acc.y + b.y);
    r.z = elu1(acc.z + b.z);
    r.w = elu1(acc.w + b.w);
    *(float4*)&Hout[node * FEAT + lane * 4] = r;
}

// ------------------------------------------------------------------
// Final projection: out[i] = dot(H[i,:], Wl) + bl. One warp per node.
__global__ __launch_bounds__(256) void k_final(const float* __restrict__ H,
                                               const float* __restrict__ Wl,
                                               const float* __restrict__ bl,
                                               float* __restrict__ out) {
    int warp = (int)((blockIdx.x * blockDim.x + threadIdx.x) >> 5);
    int lane = threadIdx.x & 31;
    if (warp >= N_NODES) return;
    float4 h = *(const float4*)&H[warp * FEAT + lane * 4];
    float4 w = *(const float4*)&Wl[lane * 4];
    float s = h.x * w.x + h.y * w.y + h.z * w.z + h.w * w.w;
    #pragma unroll
    for (int d = 16; d; d >>= 1) s += __shfl_xor_sync(0xffffffffu, s, d);
    if (lane == 0) out[warp] = s + bl[0];
}

// ------------------------------------------------------------------
extern "C" void kernel_launch(void* const* d_in, const int* in_sizes, int n_in,
                              void* d_out, int out_size) {
    const float* x  = (const float*)d_in[0];
    const float* Ws = (const float*)d_in[1];
    const float* bs = (const float*)d_in[2];
    const float* Wl = (const float*)d_in[3];
    const float* bl = (const float*)d_in[4];
    const int*   ei = (const int*)d_in[5];
    const int E = in_sizes[5] / 2;
    const int* src = ei;
    const int* dst = ei + E;
    float* out = (float*)d_out;

    float *hbuf = nullptr, *tbuf = nullptr;
    cudaGetSymbolAddress((void**)&hbuf, g_bufH);
    cudaGetSymbolAddress((void**)&tbuf, g_bufT);

    // graph structure (recomputed each call; int atomics only)
    k_zero_deg<<<(N_NODES + 255) / 256, 256>>>();
    k_count<<<(E + 255) / 256, 256>>>(dst, E);
    k_dis<<<(N_NODES + 255) / 256, 256>>>();
    k_scan<<<1, 1024>>>();
    k_fill<<<(E + 255) / 256, 256>>>(src, dst, E);

    // 3 GCN layers
    for (int i = 0; i < 3; i++) {
        const float* A = (i == 0) ? x : hbuf;
        k_gemm<<<(N_NODES + BM - 1) / BM, 256>>>(A, Ws + i * FEAT * FEAT, tbuf, N_NODES);
        k_agg<<<(N_NODES + 7) / 8, 256>>>(tbuf, bs + i * FEAT, hbuf);
    }

    k_final<<<(N_NODES + 7) / 8, 256>>>(hbuf, Wl, bl, out);
}

// round 4
// speedup vs baseline: 1.3877x; 1.3877x over previous
#include <cuda_runtime.h>
#include <cuda_bf16.h>
#include <math.h>
#include <stdint.h>

#define N_NODES 50000
#define FEAT    128
#define MAX_E   800000
#define SCAN_TILE 4096
#define SCAN_NT ((N_NODES + SCAN_TILE - 1) / SCAN_TILE)   // 13

// ---- scratch (static __device__ arrays; no runtime allocation) ----
__device__ float g_bufT[N_NODES * FEAT];
__device__ float g_bufH[N_NODES * FEAT];
__device__ int   g_deg[N_NODES];
__device__ float g_dis[N_NODES];
__device__ int   g_rowoff[N_NODES + 1];
__device__ int   g_cursor[N_NODES];
__device__ int   g_csr[MAX_E];
__device__ unsigned long long g_tilestate[SCAN_NT];

// ================= CSR construction =================
__global__ void k_zero_deg() {
    int i = blockIdx.x * blockDim.x + threadIdx.x;
    if (i < N_NODES) g_deg[i] = 0;
    if (i < SCAN_NT) g_tilestate[i] = 0ULL;
}

__global__ void k_count(const int* __restrict__ dst, int E) {
    int i = blockIdx.x * blockDim.x + threadIdx.x;
    if (i < E) atomicAdd(&g_deg[dst[i]], 1);
}

// decoupled-lookback scan: rowoff/cursor = exclusive scan of deg; also dis = rsqrt(deg+1)
__global__ __launch_bounds__(1024) void k_scan_dl() {
    __shared__ int sh_w[32];
    __shared__ unsigned int sh_prefix;
    int tid = threadIdx.x, lane = tid & 31, wid = tid >> 5;
    int tile = blockIdx.x;
    int i0 = tile * SCAN_TILE + tid * 4;

    int4 v = make_int4(0, 0, 0, 0);
    if (i0 < N_NODES) {
        v = *(const int4*)&g_deg[i0];
        float4 d;
        d.x = rsqrtf((float)(v.x + 1));
        d.y = rsqrtf((float)(v.y + 1));
        d.z = rsqrtf((float)(v.z + 1));
        d.w = rsqrtf((float)(v.w + 1));
        *(float4*)&g_dis[i0] = d;
    }
    int t0 = v.x, t1 = t0 + v.y, t2 = t1 + v.z, t3 = t2 + v.w;
    int sc = t3;
    #pragma unroll
    for (int d = 1; d < 32; d <<= 1) {
        int t = __shfl_up_sync(0xffffffffu, sc, d);
        if (lane >= d) sc += t;
    }
    if (lane == 31) sh_w[wid] = sc;
    __syncthreads();
    if (wid == 0) {
        int ws = sh_w[lane];
        #pragma unroll
        for (int d = 1; d < 32; d <<= 1) {
            int t = __shfl_up_sync(0xffffffffu, ws, d);
            if (lane >= d) ws += t;
        }
        sh_w[lane] = ws;
    }
    __syncthreads();
    int total = sh_w[31];
    int thr_excl = (wid ? sh_w[wid - 1] : 0) + sc - t3;

    if (tid == 0) {
        unsigned long long st = ((tile == 0) ? (2ULL << 32) : (1ULL << 32)) | (unsigned)total;
        atomicExch(&g_tilestate[tile], st);
    }
    if (wid == 0) {
        unsigned int prefix = 0;
        if (tile > 0) {
            bool have = lane < tile;
            unsigned long long s = 0;
            if (have) {
                do { s = *(volatile unsigned long long*)&g_tilestate[tile - 1 - lane]; }
                while ((unsigned)(s >> 32) == 0u);
            }
            unsigned flag = (unsigned)(s >> 32);
            unsigned mask = __ballot_sync(0xffffffffu, have && flag == 2u);
            int firstInc = __ffs(mask) - 1;   // exists: tile 0 is always INCLUSIVE
            unsigned contrib = (have && lane <= firstInc) ? (unsigned)s : 0u;
            #pragma unroll
            for (int d = 16; d; d >>= 1) contrib += __shfl_xor_sync(0xffffffffu, contrib, d);
            prefix = contrib;
            if (lane == 0)
                atomicExch(&g_tilestate[tile], (2ULL << 32) | (unsigned)(prefix + (unsigned)total));
        }
        if (lane == 0) sh_prefix = prefix;
    }
    __syncthreads();
    int base = (int)sh_prefix + thr_excl;
    if (i0 < N_NODES) {
        int4 o = make_int4(base, base + t0, base + t1, base + t2);
        *(int4*)&g_rowoff[i0] = o;
        *(int4*)&g_cursor[i0] = o;
    }
    if (tile == SCAN_NT - 1 && tid == 0) g_rowoff[N_NODES] = (int)sh_prefix + total;
}

__global__ void k_fill(const int* __restrict__ src, const int* __restrict__ dst, int E) {
    int i = blockIdx.x * blockDim.x + threadIdx.x;
    if (i < E) {
        int d = dst[i];
        int p = atomicAdd(&g_cursor[d], 1);
        g_csr[p] = src[i];
    }
}

// ================= bf16-split GEMM via warp mma.sync =================
// C[nrows,128] = A[nrows,128] @ W[128,128] fp32 via bf16 hi/lo split:
// D = Ahi*Whi + Alo*Whi + Ahi*Wlo (fp32 accumulate). Error ~1e-5.
//
// Block: 256 threads (8 warps), tile = 128 rows x 128 cols. Warp w owns rows
// [w*16, w*16+16). mma.sync.aligned.m16n8k16.row.col.f32.bf16.bf16.f32.
//
// W staged in SMEM fragment-major: for n-row n (0..127), kstep (0..7), t (0..3):
// two 32-bit words (b0: k=16*kstep+2t,+1 ; b1: k=16*kstep+8+2t,+1) adjacent.
// word index = n*72 + kstep*8 + t*2 + half. Row stride 72 words -> LDS.64
// bank = (8*(n&7...)) pattern conflict-free per half-warp.
#define WROW 72
#define SM_GEMM_BYTES (2 * 128 * WROW * 4)   // hi + lo = 73728 B

__device__ __forceinline__ uint32_t pack_bf2(__nv_bfloat16 a, __nv_bfloat16 b) {
    return (uint32_t)__bfloat16_as_ushort(a) | ((uint32_t)__bfloat16_as_ushort(b) << 16);
}
__device__ __forceinline__ void split2(float x, float y, uint32_t& hi, uint32_t& lo) {
    __nv_bfloat16 h0 = __float2bfloat16(x), h1 = __float2bfloat16(y);
    __nv_bfloat16 l0 = __float2bfloat16(x - __bfloat162float(h0));
    __nv_bfloat16 l1 = __float2bfloat16(y - __bfloat162float(h1));
    hi = pack_bf2(h0, h1);
    lo = pack_bf2(l0, l1);
}
__device__ __forceinline__ void mma_bf16(float* c, const uint32_t* a, uint32_t b0, uint32_t b1) {
    asm volatile(
        "mma.sync.aligned.m16n8k16.row.col.f32.bf16.bf16.f32 "
        "{%0,%1,%2,%3}, {%4,%5,%6,%7}, {%8,%9}, {%0,%1,%2,%3};"
        : "+f"(c[0]), "+f"(c[1]), "+f"(c[2]), "+f"(c[3])
        : "r"(a[0]), "r"(a[1]), "r"(a[2]), "r"(a[3]), "r"(b0), "r"(b1));
}

__global__ __launch_bounds__(256) void k_gemm_mma(const float* __restrict__ A,
                                                  const float* __restrict__ W,
                                                  float* __restrict__ C, int nrows) {
    extern __shared__ uint32_t shw[];
    uint32_t* Whi = shw;
    uint32_t* Wlo = shw + 128 * WROW;

    int tid = threadIdx.x, wid = tid >> 5, lane = tid & 31;
    int g = lane >> 2, t = lane & 3;

    // stage W: idx = p*128 + n, p = k/2 (0..63). Coalesced over n.
    for (int idx = tid; idx < 64 * 128; idx += 256) {
        int p = idx >> 7, n = idx & 127;
        int k = p * 2;
        float w0 = W[k * FEAT + n];
        float w1 = W[(k + 1) * FEAT + n];
        uint32_t hi, lo;
        split2(w0, w1, hi, lo);
        int kstep = p >> 3, q = p & 7;
        int word = n * WROW + kstep * 8 + (q & 3) * 2 + (q >> 2);
        Whi[word] = hi;
        Wlo[word] = lo;
    }
    __syncthreads();

    int r0 = blockIdx.x * 128 + wid * 16 + g;   // rows for this thread's frags
    int r1 = r0 + 8;
    bool v0 = r0 < nrows, v1 = r1 < nrows;

    float acc[16][4];
    #pragma unroll
    for (int n0 = 0; n0 < 16; n0++)
        #pragma unroll
        for (int j = 0; j < 4; j++) acc[n0][j] = 0.0f;

    #pragma unroll
    for (int kstep = 0; kstep < 8; kstep++) {
        int ka = kstep * 16 + 2 * t;
        float2 z = make_float2(0.f, 0.f);
        float2 p00 = v0 ? *(const float2*)&A[r0 * FEAT + ka]     : z;
        float2 p01 = v0 ? *(const float2*)&A[r0 * FEAT + ka + 8] : z;
        float2 p10 = v1 ? *(const float2*)&A[r1 * FEAT + ka]     : z;
        float2 p11 = v1 ? *(const float2*)&A[r1 * FEAT + ka + 8] : z;
        uint32_t ahi[4], alo[4];
        split2(p00.x, p00.y, ahi[0], alo[0]);
        split2(p10.x, p10.y, ahi[1], alo[1]);
        split2(p01.x, p01.y, ahi[2], alo[2]);
        split2(p11.x, p11.y, ahi[3], alo[3]);

        int bword = g * WROW + kstep * 8 + t * 2;   // + n0*8*WROW
        #pragma unroll
        for (int n0 = 0; n0 < 16; n0++) {
            uint2 bh = *(const uint2*)&Whi[n0 * 8 * WROW + bword];
            uint2 bl = *(const uint2*)&Wlo[n0 * 8 * WROW + bword];
            mma_bf16(acc[n0], ahi, bh.x, bh.y);
            mma_bf16(acc[n0], alo, bh.x, bh.y);
            mma_bf16(acc[n0], ahi, bl.x, bl.y);
        }
    }

    // epilogue: c0,c1 -> row r0 cols n0*8+2t..+1 ; c2,c3 -> row r1
    #pragma unroll
    for (int n0 = 0; n0 < 16; n0++) {
        int col = n0 * 8 + 2 * t;
        if (v0) *(float2*)&C[r0 * FEAT + col] = make_float2(acc[n0][0], acc[n0][1]);
        if (v1) *(float2*)&C[r1 * FEAT + col] = make_float2(acc[n0][2], acc[n0][3]);
    }
}

// ================= aggregation (one warp per dst node) =================
__device__ __forceinline__ float elu1(float v) { return v > 0.0f ? v : expm1f(v); }

__global__ __launch_bounds__(256) void k_agg(const float* __restrict__ T,
                                             const float* __restrict__ bias,
                                             float* __restrict__ Hout) {
    int warp = (int)((blockIdx.x * blockDim.x + threadIdx.x) >> 5);
    int lane = threadIdx.x & 31;
    if (warp >= N_NODES) return;
    int node = warp;
    float dd = g_dis[node];

    float4 acc = *(const float4*)&T[node * FEAT + lane * 4];
    float ws = dd * dd;
    acc.x *= ws; acc.y *= ws; acc.z *= ws; acc.w *= ws;

    int beg = g_rowoff[node];
    int end = g_rowoff[node + 1];
    int e = beg;
    for (; e + 1 < end; e += 2) {
        int s0 = g_csr[e];
        int s1 = g_csr[e + 1];
        float w0 = g_dis[s0] * dd;
        float w1 = g_dis[s1] * dd;
        float4 vv0 = *(const float4*)&T[s0 * FEAT + lane * 4];
        float4 vv1 = *(const float4*)&T[s1 * FEAT + lane * 4];
        acc.x = fmaf(w0, vv0.x, fmaf(w1, vv1.x, acc.x));
        acc.y = fmaf(w0, vv0.y, fmaf(w1, vv1.y, acc.y));
        acc.z = fmaf(w0, vv0.z, fmaf(w1, vv1.z, acc.z));
        acc.w = fmaf(w0, vv0.w, fmaf(w1, vv1.w, acc.w));
    }
    if (e < end) {
        int s0 = g_csr[e];
        float w0 = g_dis[s0] * dd;
        float4 vv0 = *(const float4*)&T[s0 * FEAT + lane * 4];
        acc.x = fmaf(w0, vv0.x, acc.x);
        acc.y = fmaf(w0, vv0.y, acc.y);
        acc.z = fmaf(w0, vv0.z, acc.z);
        acc.w = fmaf(w0, vv0.w, acc.w);
    }

    float4 b = *(const float4*)&bias[lane * 4];
    float4 r;
    r.x = elu1(acc.x + b.x);
    r.y = elu1(acc.y + b.y);
    r.z = elu1(acc.z + b.z);
    r.w = elu1(acc.w + b.w);
    *(float4*)&Hout[node * FEAT + lane * 4] = r;
}

// ================= final projection =================
__global__ __launch_bounds__(256) void k_final(const float* __restrict__ H,
                                               const float* __restrict__ Wl,
                                               const float* __restrict__ bl,
                                               float* __restrict__ out) {
    int warp = (int)((blockIdx.x * blockDim.x + threadIdx.x) >> 5);
    int lane = threadIdx.x & 31;
    if (warp >= N_NODES) return;
    float4 h = *(const float4*)&H[warp * FEAT + lane * 4];
    float4 w = *(const float4*)&Wl[lane * 4];
    float s = h.x * w.x + h.y * w.y + h.z * w.z + h.w * w.w;
    #pragma unroll
    for (int d = 16; d; d >>= 1) s += __shfl_xor_sync(0xffffffffu, s, d);
    if (lane == 0) out[warp] = s + bl[0];
}

// ================= launch =================
extern "C" void kernel_launch(void* const* d_in, const int* in_sizes, int n_in,
                              void* d_out, int out_size) {
    const float* x  = (const float*)d_in[0];
    const float* Ws = (const float*)d_in[1];
    const float* bs = (const float*)d_in[2];
    const float* Wl = (const float*)d_in[3];
    const float* bl = (const float*)d_in[4];
    const int*   ei = (const int*)d_in[5];
    const int E = in_sizes[5] / 2;
    const int* src = ei;
    const int* dst = ei + E;
    float* out = (float*)d_out;

    float *hbuf = nullptr, *tbuf = nullptr;
    cudaGetSymbolAddress((void**)&hbuf, g_bufH);
    cudaGetSymbolAddress((void**)&tbuf, g_bufT);

    cudaFuncSetAttribute(k_gemm_mma, cudaFuncAttributeMaxDynamicSharedMemorySize, SM_GEMM_BYTES);

    // graph structure
    k_zero_deg<<<(N_NODES + 255) / 256, 256>>>();
    k_count<<<(E + 255) / 256, 256>>>(dst, E);
    k_scan_dl<<<SCAN_NT, 1024>>>();
    k_fill<<<(E + 255) / 256, 256>>>(src, dst, E);

    const int ntiles = (N_NODES + 127) / 128;
    for (int i = 0; i < 3; i++) {
        const float* Ain = (i == 0) ? x : hbuf;
        k_gemm_mma<<<ntiles, 256, SM_GEMM_BYTES>>>(Ain, Ws + i * FEAT * FEAT, tbuf, N_NODES);
        k_agg<<<(N_NODES + 7) / 8, 256>>>(tbuf, bs + i * FEAT, hbuf);
    }

    k_final<<<(N_NODES + 7) / 8, 256>>>(hbuf, Wl, bl, out);
}

// round 5
// speedup vs baseline: 1.5259x; 1.0996x over previous
#include <cuda_runtime.h>
#include <cuda_bf16.h>
#include <cuda_fp16.h>
#include <math.h>
#include <stdint.h>

#define N_NODES 50000
#define FEAT    128
#define MAX_E   800000
#define SCAN_TILE 4096
#define SCAN_NT ((N_NODES + SCAN_TILE - 1) / SCAN_TILE)   // 13

// ---- scratch (static __device__ arrays; no runtime allocation) ----
__device__ __half g_bufT[N_NODES * FEAT];   // post-GEMM features (fp16)
__device__ float  g_bufH[N_NODES * FEAT];   // post-aggregation features (fp32)
__device__ int   g_deg[N_NODES];
__device__ float g_dis[N_NODES];
__device__ int   g_rowoff[N_NODES + 1];
__device__ int   g_cursor[N_NODES];
__device__ int   g_csr[MAX_E];
__device__ unsigned long long g_tilestate[SCAN_NT];

// ================= CSR construction =================
__global__ void k_zero_deg() {
    int i = blockIdx.x * blockDim.x + threadIdx.x;
    if (i < N_NODES) g_deg[i] = 0;
    if (i < SCAN_NT) g_tilestate[i] = 0ULL;
}

__global__ void k_count(const int* __restrict__ dst, int E) {
    int i = blockIdx.x * blockDim.x + threadIdx.x;
    if (i < E) atomicAdd(&g_deg[dst[i]], 1);
}

// decoupled-lookback scan: rowoff/cursor = exclusive scan of deg; also dis = rsqrt(deg+1)
__global__ __launch_bounds__(1024) void k_scan_dl() {
    __shared__ int sh_w[32];
    __shared__ unsigned int sh_prefix;
    int tid = threadIdx.x, lane = tid & 31, wid = tid >> 5;
    int tile = blockIdx.x;
    int i0 = tile * SCAN_TILE + tid * 4;

    int4 v = make_int4(0, 0, 0, 0);
    if (i0 < N_NODES) {
        v = *(const int4*)&g_deg[i0];
        float4 d;
        d.x = rsqrtf((float)(v.x + 1));
        d.y = rsqrtf((float)(v.y + 1));
        d.z = rsqrtf((float)(v.z + 1));
        d.w = rsqrtf((float)(v.w + 1));
        *(float4*)&g_dis[i0] = d;
    }
    int t0 = v.x, t1 = t0 + v.y, t2 = t1 + v.z, t3 = t2 + v.w;
    int sc = t3;
    #pragma unroll
    for (int d = 1; d < 32; d <<= 1) {
        int t = __shfl_up_sync(0xffffffffu, sc, d);
        if (lane >= d) sc += t;
    }
    if (lane == 31) sh_w[wid] = sc;
    __syncthreads();
    if (wid == 0) {
        int ws = sh_w[lane];
        #pragma unroll
        for (int d = 1; d < 32; d <<= 1) {
            int t = __shfl_up_sync(0xffffffffu, ws, d);
            if (lane >= d) ws += t;
        }
        sh_w[lane] = ws;
    }
    __syncthreads();
    int total = sh_w[31];
    int thr_excl = (wid ? sh_w[wid - 1] : 0) + sc - t3;

    if (tid == 0) {
        unsigned long long st = ((tile == 0) ? (2ULL << 32) : (1ULL << 32)) | (unsigned)total;
        atomicExch(&g_tilestate[tile], st);
    }
    if (wid == 0) {
        unsigned int prefix = 0;
        if (tile > 0) {
            bool have = lane < tile;
            unsigned long long s = 0;
            if (have) {
                do { s = *(volatile unsigned long long*)&g_tilestate[tile - 1 - lane]; }
                while ((unsigned)(s >> 32) == 0u);
            }
            unsigned flag = (unsigned)(s >> 32);
            unsigned mask = __ballot_sync(0xffffffffu, have && flag == 2u);
            int firstInc = __ffs(mask) - 1;   // exists: tile 0 is always INCLUSIVE
            unsigned contrib = (have && lane <= firstInc) ? (unsigned)s : 0u;
            #pragma unroll
            for (int d = 16; d; d >>= 1) contrib += __shfl_xor_sync(0xffffffffu, contrib, d);
            prefix = contrib;
            if (lane == 0)
                atomicExch(&g_tilestate[tile], (2ULL << 32) | (unsigned)(prefix + (unsigned)total));
        }
        if (lane == 0) sh_prefix = prefix;
    }
    __syncthreads();
    int base = (int)sh_prefix + thr_excl;
    if (i0 < N_NODES) {
        int4 o = make_int4(base, base + t0, base + t1, base + t2);
        *(int4*)&g_rowoff[i0] = o;
        *(int4*)&g_cursor[i0] = o;
    }
    if (tile == SCAN_NT - 1 && tid == 0) g_rowoff[N_NODES] = (int)sh_prefix + total;
}

__global__ void k_fill(const int* __restrict__ src, const int* __restrict__ dst, int E) {
    int i = blockIdx.x * blockDim.x + threadIdx.x;
    if (i < E) {
        int d = dst[i];
        int p = atomicAdd(&g_cursor[d], 1);
        g_csr[p] = src[i];
    }
}

// ================= bf16-split GEMM via warp mma.sync =================
// C[nrows,128] = A[nrows,128] @ W[128,128], fp32 math via bf16 hi/lo split:
// D = Ahi*Whi + Alo*Whi + Ahi*Wlo (fp32 accumulate). Output stored fp16.
#define WROW 72
#define SM_GEMM_BYTES (2 * 128 * WROW * 4)   // hi + lo = 73728 B

__device__ __forceinline__ uint32_t pack_bf2(__nv_bfloat16 a, __nv_bfloat16 b) {
    return (uint32_t)__bfloat16_as_ushort(a) | ((uint32_t)__bfloat16_as_ushort(b) << 16);
}
__device__ __forceinline__ void split2(float x, float y, uint32_t& hi, uint32_t& lo) {
    __nv_bfloat16 h0 = __float2bfloat16(x), h1 = __float2bfloat16(y);
    __nv_bfloat16 l0 = __float2bfloat16(x - __bfloat162float(h0));
    __nv_bfloat16 l1 = __float2bfloat16(y - __bfloat162float(h1));
    hi = pack_bf2(h0, h1);
    lo = pack_bf2(l0, l1);
}
__device__ __forceinline__ void mma_bf16(float* c, const uint32_t* a, uint32_t b0, uint32_t b1) {
    asm volatile(
        "mma.sync.aligned.m16n8k16.row.col.f32.bf16.bf16.f32 "
        "{%0,%1,%2,%3}, {%4,%5,%6,%7}, {%8,%9}, {%0,%1,%2,%3};"
        : "+f"(c[0]), "+f"(c[1]), "+f"(c[2]), "+f"(c[3])
        : "r"(a[0]), "r"(a[1]), "r"(a[2]), "r"(a[3]), "r"(b0), "r"(b1));
}

__global__ __launch_bounds__(256) void k_gemm_mma(const float* __restrict__ A,
                                                  const float* __restrict__ W,
                                                  __half* __restrict__ C, int nrows) {
    extern __shared__ uint32_t shw[];
    uint32_t* Whi = shw;
    uint32_t* Wlo = shw + 128 * WROW;

    int tid = threadIdx.x, wid = tid >> 5, lane = tid & 31;
    int g = lane >> 2, t = lane & 3;

    // stage W: idx = p*128 + n, p = k/2 (0..63). Coalesced over n.
    for (int idx = tid; idx < 64 * 128; idx += 256) {
        int p = idx >> 7, n = idx & 127;
        int k = p * 2;
        float w0 = W[k * FEAT + n];
        float w1 = W[(k + 1) * FEAT + n];
        uint32_t hi, lo;
        split2(w0, w1, hi, lo);
        int kstep = p >> 3, q = p & 7;
        int word = n * WROW + kstep * 8 + (q & 3) * 2 + (q >> 2);
        Whi[word] = hi;
        Wlo[word] = lo;
    }
    __syncthreads();

    int r0 = blockIdx.x * 128 + wid * 16 + g;   // rows for this thread's frags
    int r1 = r0 + 8;
    bool v0 = r0 < nrows, v1 = r1 < nrows;

    float acc[16][4];
    #pragma unroll
    for (int n0 = 0; n0 < 16; n0++)
        #pragma unroll
        for (int j = 0; j < 4; j++) acc[n0][j] = 0.0f;

    #pragma unroll
    for (int kstep = 0; kstep < 8; kstep++) {
        int ka = kstep * 16 + 2 * t;
        float2 z = make_float2(0.f, 0.f);
        float2 p00 = v0 ? *(const float2*)&A[r0 * FEAT + ka]     : z;
        float2 p01 = v0 ? *(const float2*)&A[r0 * FEAT + ka + 8] : z;
        float2 p10 = v1 ? *(const float2*)&A[r1 * FEAT + ka]     : z;
        float2 p11 = v1 ? *(const float2*)&A[r1 * FEAT + ka + 8] : z;
        uint32_t ahi[4], alo[4];
        split2(p00.x, p00.y, ahi[0], alo[0]);
        split2(p10.x, p10.y, ahi[1], alo[1]);
        split2(p01.x, p01.y, ahi[2], alo[2]);
        split2(p11.x, p11.y, ahi[3], alo[3]);

        int bword = g * WROW + kstep * 8 + t * 2;   // + n0*8*WROW
        #pragma unroll
        for (int n0 = 0; n0 < 16; n0++) {
            uint2 bh = *(const uint2*)&Whi[n0 * 8 * WROW + bword];
            uint2 bl = *(const uint2*)&Wlo[n0 * 8 * WROW + bword];
            mma_bf16(acc[n0], ahi, bh.x, bh.y);
            mma_bf16(acc[n0], alo, bh.x, bh.y);
            mma_bf16(acc[n0], ahi, bl.x, bl.y);
        }
    }

    // epilogue: write fp16. c0,c1 -> row r0 cols n0*8+2t..+1 ; c2,c3 -> row r1
    #pragma unroll
    for (int n0 = 0; n0 < 16; n0++) {
        int col = n0 * 8 + 2 * t;
        if (v0) *(__half2*)&C[r0 * FEAT + col] = __floats2half2_rn(acc[n0][0], acc[n0][1]);
        if (v1) *(__half2*)&C[r1 * FEAT + col] = __floats2half2_rn(acc[n0][2], acc[n0][3]);
    }
}

// ================= aggregation (one warp per dst node, fp16 gather) ======
__device__ __forceinline__ float elu1(float v) { return v > 0.0f ? v : expm1f(v); }

__device__ __forceinline__ float4 ld_row_h(const __half* __restrict__ T, int s, int lane) {
    uint2 u = *(const uint2*)(T + s * FEAT + lane * 4);
    __half2 h0 = *(__half2*)&u.x;
    __half2 h1 = *(__half2*)&u.y;
    float2 f0 = __half22float2(h0);
    float2 f1 = __half22float2(h1);
    return make_float4(f0.x, f0.y, f1.x, f1.y);
}

// FUSE_FINAL=0: Hout = ELU(acc+bias). FUSE_FINAL=1: out = ELU(acc+bias)@Wl + bl.
template<int FUSE_FINAL>
__global__ __launch_bounds__(256) void k_agg_t(const __half* __restrict__ T,
                                               const float* __restrict__ bias,
                                               float* __restrict__ Hout,
                                               const float* __restrict__ Wl,
                                               const float* __restrict__ bl,
                                               float* __restrict__ out) {
    int warp = (int)((blockIdx.x * blockDim.x + threadIdx.x) >> 5);
    int lane = threadIdx.x & 31;
    if (warp >= N_NODES) return;
    int node = warp;
    float dd = g_dis[node];

    float4 acc = ld_row_h(T, node, lane);
    float ws = dd * dd;                        // self-loop weight
    acc.x *= ws; acc.y *= ws; acc.z *= ws; acc.w *= ws;

    int beg = g_rowoff[node];
    int end = g_rowoff[node + 1];
    int e = beg;
    for (; e + 3 < end; e += 4) {
        int s0 = g_csr[e],     s1 = g_csr[e + 1];
        int s2 = g_csr[e + 2], s3 = g_csr[e + 3];
        float w0 = g_dis[s0] * dd, w1 = g_dis[s1] * dd;
        float w2 = g_dis[s2] * dd, w3 = g_dis[s3] * dd;
        float4 v0 = ld_row_h(T, s0, lane);
        float4 v1 = ld_row_h(T, s1, lane);
        float4 v2 = ld_row_h(T, s2, lane);
        float4 v3 = ld_row_h(T, s3, lane);
        acc.x = fmaf(w0, v0.x, fmaf(w1, v1.x, fmaf(w2, v2.x, fmaf(w3, v3.x, acc.x))));
        acc.y = fmaf(w0, v0.y, fmaf(w1, v1.y, fmaf(w2, v2.y, fmaf(w3, v3.y, acc.y))));
        acc.z = fmaf(w0, v0.z, fmaf(w1, v1.z, fmaf(w2, v2.z, fmaf(w3, v3.z, acc.z))));
        acc.w = fmaf(w0, v0.w, fmaf(w1, v1.w, fmaf(w2, v2.w, fmaf(w3, v3.w, acc.w))));
    }
    for (; e < end; e++) {
        int s0 = g_csr[e];
        float w0 = g_dis[s0] * dd;
        float4 v0 = ld_row_h(T, s0, lane);
        acc.x = fmaf(w0, v0.x, acc.x);
        acc.y = fmaf(w0, v0.y, acc.y);
        acc.z = fmaf(w0, v0.z, acc.z);
        acc.w = fmaf(w0, v0.w, acc.w);
    }

    float4 b = *(const float4*)&bias[lane * 4];
    float4 r;
    r.x = elu1(acc.x + b.x);
    r.y = elu1(acc.y + b.y);
    r.z = elu1(acc.z + b.z);
    r.w = elu1(acc.w + b.w);

    if (FUSE_FINAL) {
        float4 w = *(const float4*)&Wl[lane * 4];
        float s = r.x * w.x + r.y * w.y + r.z * w.z + r.w * w.w;
        #pragma unroll
        for (int d = 16; d; d >>= 1) s += __shfl_xor_sync(0xffffffffu, s, d);
        if (lane == 0) out[node] = s + bl[0];
    } else {
        *(float4*)&Hout[node * FEAT + lane * 4] = r;
    }
}

// ================= launch =================
extern "C" void kernel_launch(void* const* d_in, const int* in_sizes, int n_in,
                              void* d_out, int out_size) {
    const float* x  = (const float*)d_in[0];
    const float* Ws = (const float*)d_in[1];
    const float* bs = (const float*)d_in[2];
    const float* Wl = (const float*)d_in[3];
    const float* bl = (const float*)d_in[4];
    const int*   ei = (const int*)d_in[5];
    const int E = in_sizes[5] / 2;
    const int* src = ei;
    const int* dst = ei + E;
    float* out = (float*)d_out;

    float* hbuf = nullptr;
    __half* tbuf = nullptr;
    cudaGetSymbolAddress((void**)&hbuf, g_bufH);
    cudaGetSymbolAddress((void**)&tbuf, g_bufT);

    cudaFuncSetAttribute(k_gemm_mma, cudaFuncAttributeMaxDynamicSharedMemorySize, SM_GEMM_BYTES);

    // graph structure
    k_zero_deg<<<(N_NODES + 255) / 256, 256>>>();
    k_count<<<(E + 255) / 256, 256>>>(dst, E);
    k_scan_dl<<<SCAN_NT, 1024>>>();
    k_fill<<<(E + 255) / 256, 256>>>(src, dst, E);

    const int ntiles = (N_NODES + 127) / 128;
    const int nagg   = (N_NODES + 7) / 8;
    for (int i = 0; i < 3; i++) {
        const float* Ain = (i == 0) ? x : hbuf;
        k_gemm_mma<<<ntiles, 256, SM_GEMM_BYTES>>>(Ain, Ws + i * FEAT * FEAT, tbuf, N_NODES);
        if (i < 2)
            k_agg_t<0><<<nagg, 256>>>(tbuf, bs + i * FEAT, hbuf, nullptr, nullptr, nullptr);
        else
            k_agg_t<1><<<nagg, 256>>>(tbuf, bs + i * FEAT, nullptr, Wl, bl, out);
    }
}